// round 12
// baseline (speedup 1.0000x reference)
#include <cuda_runtime.h>

// Lifting wavelet v12: SINGLE kernel. Shuffle-halo window (v10: L1 51%, 1.0x
// read amplification) + per-block SMEM taps read via volatile LDS.
// volatile prevents ptxas from hoisting/CSE-ing tap loads into long-lived
// registers (the failure of LDG taps in v6/v7/v11): each tap is one LDS,
// live for 4 FMAs, then dead -> register count stays near v10's 36 without
// the ~5us setup-kernel graph node that LDC taps required.
// input: (4096, 8192) f32. even = in[:, ::2], odd = in[:, 1::2] (4096 each).
// wavelet[j] = scaling_rec[7-j] * (j odd ? -1 : +1)
// odd_out[k]  = odd[k]  - sum_j wavelet[j] * even[(k-j) mod 4096]
// even_out[k] = even[k] - sum_j scaling[j] * odd[(k-j) mod 4096]
// Output: [even_updated | odd_updated], each 4096x4096 f32.

#define ROWS    4096
#define ROWLEN  8192
#define HALF    4096
#define NTH     256
#define FMASK   (ROWLEN - 1)

__global__ __launch_bounds__(NTH, 6)   // <=42 regs
void wavelet_fwd_v12(const float* __restrict__ in,
                     const float* __restrict__ scaling,
                     const float* __restrict__ scaling_rec,
                     float* __restrict__ out)
{
    __shared__ float sT[16];           // [0..7] wavelet, [8..15] scaling

    const int g    = blockIdx.x * NTH + threadIdx.x;  // 0 .. 4M-1
    const int row  = g >> 10;                          // 1024 threads per row
    const int lk   = (g & 1023) << 2;                  // pair base: 0..4092
    const int lane = threadIdx.x & 31;

    const float* rowp = in + (size_t)row * ROWLEN;

    // Per-block tap computation (threads 0..15; LDGs overlap window LDGs).
    if (threadIdx.x < 16) {
        int t = threadIdx.x;
        float v;
        if (t < 8) {
            float w = scaling_rec[7 - t];
            v = (t & 1) ? -w : w;      // wavelet[t]
        } else {
            v = scaling[t - 8];
        }
        sT[t] = v;
    }

    // wnd[j] = row[(2lk-16+j) mod 8192], j = 0..23.
    float wnd[24];

    // Own 8 floats: row[2lk .. 2lk+7] -> wnd[16..23]. Amplification 1.0x.
    {
        const float4* p = reinterpret_cast<const float4*>(rowp + 2 * lk);
        float4 v0 = p[0];
        float4 v1 = p[1];
        wnd[16] = v0.x; wnd[17] = v0.y; wnd[18] = v0.z; wnd[19] = v0.w;
        wnd[20] = v1.x; wnd[21] = v1.y; wnd[22] = v1.z; wnd[23] = v1.w;
    }

    // Halo via shuffles (consecutive lanes own consecutive 4-pair segments;
    // blocks never span rows):
    //   lane-1 owns row[2lk-8 .. 2lk-1]  -> wnd[8..15]
    //   lane-2 owns row[2lk-16 .. 2lk-9] -> wnd[0..7]
#pragma unroll
    for (int i = 0; i < 8; i++) {
        wnd[8 + i] = __shfl_up_sync(0xffffffffu, wnd[16 + i], 1);
        wnd[i]     = __shfl_up_sync(0xffffffffu, wnd[16 + i], 2);
    }

    // Lanes 0,1 fix up what shuffles couldn't provide (circular via & FMASK).
    if (lane < 2) {
#pragma unroll
        for (int q = 0; q < 2; q++) {
            int fi = (2 * lk - 16 + 4 * q) & FMASK;
            float4 v = *reinterpret_cast<const float4*>(rowp + fi);
            wnd[4*q+0] = v.x; wnd[4*q+1] = v.y; wnd[4*q+2] = v.z; wnd[4*q+3] = v.w;
        }
        if (lane == 0) {
#pragma unroll
            for (int q = 0; q < 2; q++) {
                int fi = (2 * lk - 8 + 4 * q) & FMASK;
                float4 v = *reinterpret_cast<const float4*>(rowp + fi);
                wnd[8+4*q+0] = v.x; wnd[8+4*q+1] = v.y;
                wnd[8+4*q+2] = v.z; wnd[8+4*q+3] = v.w;
            }
        }
    }

    __syncthreads();                    // taps visible; window loads already issued

    volatile const float* vT = sT;      // volatile: one LDS per tap, no pinning
    const size_t obase = (size_t)row * HALF + lk;

    // --- Odd outputs: rO[m] = wnd[2m+17] - sum_j wavelet[j]*wnd[2m+16-2j] ---
    {
        float a0 = wnd[17], a1 = wnd[19], a2 = wnd[21], a3 = wnd[23];
#pragma unroll
        for (int j = 0; j < 8; j++) {
            float wj = vT[j];           // single LDS, short live range
            a0 -= wj * wnd[16 - 2*j];
            a1 -= wj * wnd[18 - 2*j];
            a2 -= wj * wnd[20 - 2*j];
            a3 -= wj * wnd[22 - 2*j];
        }
        *reinterpret_cast<float4*>(out + (size_t)ROWS * HALF + obase) =
            make_float4(a0, a1, a2, a3);
    }

    // --- Even outputs: rE[m] = wnd[2m+16] - sum_j scaling[j]*wnd[2m+17-2j] ---
    {
        float e0 = wnd[16], e1 = wnd[18], e2 = wnd[20], e3 = wnd[22];
#pragma unroll
        for (int j = 0; j < 8; j++) {
            float cj = vT[8 + j];
            e0 -= cj * wnd[17 - 2*j];
            e1 -= cj * wnd[19 - 2*j];
            e2 -= cj * wnd[21 - 2*j];
            e3 -= cj * wnd[23 - 2*j];
        }
        *reinterpret_cast<float4*>(out + obase) =
            make_float4(e0, e1, e2, e3);
    }
}

extern "C" void kernel_launch(void* const* d_in, const int* in_sizes, int n_in,
                              void* d_out, int out_size)
{
    const float* input       = (const float*)d_in[0];
    const float* scaling     = (const float*)d_in[1];
    const float* scaling_rec = (const float*)d_in[2];
    float* out = (float*)d_out;

    const int total_threads = ROWS * (HALF / 4);       // 4M
    wavelet_fwd_v12<<<total_threads / NTH, NTH>>>(input, scaling, scaling_rec, out);
}